// round 5
// baseline (speedup 1.0000x reference)
#include <cuda_runtime.h>
#include <stdint.h>

#define N_BOXES 25200
#define NCLS 80
#define MAXB 100
#define CAP 384          // max candidates per window
#define W   12           // CAP/32 bitmask words per row
#define SORTP_MAX 512
#define NBINS 256
#define TARGET 320

// Output layout (float32 concatenation of the reference tuple):
//   [0, 100800)               boxes copy               (1, 25200, 4)
//   [100800, 2116800)         box_scores transposed    (1, 80, 25200)
//   [2116800, 2140800)        nms_final as f32         (1, 8000, 3)
#define OFF_T   100800
#define OFF_NMS (100800 + NCLS * N_BOXES)

// ---------------------------------------------------------------------------
// Kernel 1: copy boxes + transpose scores [25200,80] -> [80,25200]
// ---------------------------------------------------------------------------
#define TBLK 197  // transpose blocks, 128 rows each (197*128 >= 25200)

__global__ void prep_kernel(const float* __restrict__ boxes,
                            const float* __restrict__ scores,
                            float* __restrict__ out) {
    if (blockIdx.x < TBLK) {
        __shared__ float tile[128][81];  // pad to 81: stride coprime with 32 banks
        int n0 = blockIdx.x * 128;
        int rows = min(128, N_BOXES - n0);
        for (int i = threadIdx.x; i < rows * 80; i += blockDim.x)
            tile[i / 80][i % 80] = scores[n0 * 80 + i];
        __syncthreads();
        float* outT = out + OFF_T;
        for (int i = threadIdx.x; i < 80 * rows; i += blockDim.x) {
            int c = i / rows, dn = i % rows;
            outT[c * N_BOXES + n0 + dn] = tile[dn][c];
        }
    } else {
        int b = blockIdx.x - TBLK;
        const float4* src = (const float4*)boxes;
        float4* dst = (float4*)out;
        int stride = (gridDim.x - TBLK) * blockDim.x;
        for (int i = b * blockDim.x + threadIdx.x; i < N_BOXES; i += stride)
            dst[i] = src[i];
    }
}

// ---------------------------------------------------------------------------
// Kernel 2: one block per class. Sorted window + parallel mask NMS.
// ---------------------------------------------------------------------------
__global__ __launch_bounds__(1024, 1) void nms_kernel(const float* __restrict__ boxes,
                                                      float* __restrict__ out) {
    const int c = blockIdx.x;
    const float* row = out + OFF_T + c * N_BOXES;      // transposed scores
    float* nmsout = out + OFF_NMS + c * (MAXB * 3);

    __shared__ int hist[NBINS];
    __shared__ unsigned long long key[SORTP_MAX];
    __shared__ int bidx[CAP];
    __shared__ float by1[CAP], bx1[CAP], by2[CAP], bx2[CAP], bar[CAP];
    __shared__ unsigned int mask[CAP * W];             // mask[q][chunk]
    __shared__ unsigned int removed[W];
    __shared__ float sy1[MAXB], sx1[MAXB], sy2[MAXB], sx2[MAXB], sar[MAXB];
    __shared__ int sidx[MAXB];
    __shared__ int sh_m, sh_sel, sh_lo, sh_hi;

    const int tid = threadIdx.x;
    const int wid = tid >> 5;
    const int lane = tid & 31;

    for (int i = tid; i < NBINS; i += 1024) hist[i] = 0;
    if (tid == 0) { sh_sel = 0; sh_hi = NBINS; }
    __syncthreads();

    // Histogram of scores >= 0.6 into 256 bins over [0.6, 1.0)
    for (int n = tid; n < N_BOXES; n += 1024) {
        float s = row[n];
        if (s >= 0.6f) {
            int b = (int)((s - 0.6f) * 640.0f);
            b = max(0, min(NBINS - 1, b));
            atomicAdd(&hist[b], 1);
        }
    }
    __syncthreads();

    // Window loop (almost always a single iteration)
    while (sh_sel < MAXB && sh_hi > 0) {
        if (tid == 0) {
            int hi = sh_hi, lo = hi, acc = 0;
            while (lo > 0 && acc + hist[lo - 1] <= TARGET) { acc += hist[lo - 1]; lo--; }
            if (lo == hi) lo = hi - 1;   // oversized single bin: take it anyway
            sh_lo = lo;
            sh_m = 0;
        }
        if (tid < W) removed[tid] = 0u;
        __syncthreads();
        const int lo = sh_lo, hi = sh_hi;

        // Gather keys for candidates in bin window [lo, hi)
        for (int n = tid; n < N_BOXES; n += 1024) {
            float s = row[n];
            if (s >= 0.6f) {
                int b = (int)((s - 0.6f) * 640.0f);
                b = max(0, min(NBINS - 1, b));
                if (b >= lo && b < hi) {
                    int p = atomicAdd(&sh_m, 1);
                    if (p < CAP) {
                        unsigned int sb = __float_as_uint(s);  // positive floats: monotonic
                        key[p] = ((unsigned long long)sb << 32) | (unsigned int)(~(unsigned int)n);
                    }
                }
            }
        }
        __syncthreads();
        const int m = min(sh_m, CAP);

        if (m > 0) {
            int P = 1; while (P < m) P <<= 1; if (P < 2) P = 2;
            for (int i = m + tid; i < P; i += 1024) key[i] = 0ULL;  // sink padding
            __syncthreads();

            // Bitonic sort descending, P <= 512
            for (int k = 2; k <= P; k <<= 1) {
                for (int j = k >> 1; j > 0; j >>= 1) {
                    for (int i = tid; i < P; i += 1024) {
                        int ixj = i ^ j;
                        if (ixj > i) {
                            unsigned long long a = key[i], b2 = key[ixj];
                            bool up = ((i & k) == 0);
                            if (up ? (a < b2) : (a > b2)) { key[i] = b2; key[ixj] = a; }
                        }
                    }
                    __syncthreads();
                }
            }

            // Gather boxes for sorted candidates
            for (int r = tid; r < m; r += 1024) {
                int n = (int)(~(unsigned int)(key[r] & 0xffffffffULL));
                bidx[r] = n;
                float y1 = boxes[n * 4 + 0], x1 = boxes[n * 4 + 1];
                float y2 = boxes[n * 4 + 2], x2 = boxes[n * 4 + 3];
                by1[r] = y1; bx1[r] = x1; by2[r] = y2; bx2[r] = x2;
                bar[r] = __fmul_rn(y2 - y1, x2 - x1);  // exact ref semantics, no FMA
            }
            __syncthreads();

            // Cross-window: pre-remove candidates suppressed by already-selected
            const int sel0 = sh_sel;
            if (sel0 > 0) {
                for (int r = wid; r < m; r += 32) {
                    float cy1 = by1[r], cx1 = bx1[r], cy2 = by2[r], cx2 = bx2[r], ca = bar[r];
                    bool sup = false;
                    for (int t = lane; t < sel0; t += 32) {
                        float iy1 = fmaxf(sy1[t], cy1);
                        float ix1 = fmaxf(sx1[t], cx1);
                        float iy2 = fminf(sy2[t], cy2);
                        float ix2 = fminf(sx2[t], cx2);
                        float inter = __fmul_rn(fmaxf(iy2 - iy1, 0.0f), fmaxf(ix2 - ix1, 0.0f));
                        float uni = sar[t] + ca - inter;
                        float iou = __fdiv_rn(inter, fmaxf(uni, 1e-9f));
                        if (iou > 0.5f) sup = true;
                    }
                    if (__ballot_sync(0xffffffffu, sup) != 0u && lane == 0)
                        atomicOr(&removed[r >> 5], 1u << (r & 31));
                }
            }

            // Phase A: pairwise suppression masks. Warp per row q; one ballot
            // per 32-candidate chunk. Row q written only by its warp -> plain store.
            for (int q = wid; q < m; q += 32) {
                float qy1 = by1[q], qx1 = bx1[q], qy2 = by2[q], qx2 = bx2[q], qa = bar[q];
                for (int r0 = 0; r0 < W * 32; r0 += 32) {
                    int r = r0 + lane;
                    bool pred = false;
                    if (r > q && r < m) {
                        float iy1 = fmaxf(qy1, by1[r]);
                        float ix1 = fmaxf(qx1, bx1[r]);
                        float iy2 = fminf(qy2, by2[r]);
                        float ix2 = fminf(qx2, bx2[r]);
                        float inter = __fmul_rn(fmaxf(iy2 - iy1, 0.0f), fmaxf(ix2 - ix1, 0.0f));
                        float uni = qa + bar[r] - inter;   // selected-first order, adds only
                        float iou = __fdiv_rn(inter, fmaxf(uni, 1e-9f));
                        pred = (iou > 0.5f);
                    }
                    unsigned int bits = __ballot_sync(0xffffffffu, pred);
                    if (lane == 0) mask[q * W + (r0 >> 5)] = bits;
                }
            }
            __syncthreads();

            // Phase B: serial bitmask greedy scan (warp 0)
            if (tid < 32) {
                int sel = sh_sel;
                for (int q = 0; q < m && sel < MAXB; ++q) {
                    unsigned int rw = removed[q >> 5];     // broadcast smem read
                    if (!((rw >> (q & 31)) & 1u)) {
                        if (lane == 0) {
                            sidx[sel] = bidx[q];
                            sy1[sel] = by1[q]; sx1[sel] = bx1[q];
                            sy2[sel] = by2[q]; sx2[sel] = bx2[q];
                            sar[sel] = bar[q];
                        }
                        if (lane < W) removed[lane] |= mask[q * W + lane];
                        sel++;
                    }
                    __syncwarp();
                }
                if (lane == 0) sh_sel = sel;
            }
        }
        __syncthreads();
        if (tid == 0) sh_hi = sh_lo;
        __syncthreads();
    }

    // Emit nms_final rows for this class: [0, c, idx] or [-1,-1,-1]
    const int sel = sh_sel;
    for (int j = tid; j < MAXB; j += 1024) {
        float* o = nmsout + j * 3;
        if (j < sel) { o[0] = 0.0f; o[1] = (float)c; o[2] = (float)sidx[j]; }
        else         { o[0] = -1.0f; o[1] = -1.0f; o[2] = -1.0f; }
    }
}

// ---------------------------------------------------------------------------
extern "C" void kernel_launch(void* const* d_in, const int* in_sizes, int n_in,
                              void* d_out, int out_size) {
    const float* boxes  = (const float*)d_in[0];   // (25200, 4)
    const float* scores = (const float*)d_in[1];   // (25200, 80)
    float* out = (float*)d_out;

    prep_kernel<<<TBLK + 25, 256>>>(boxes, scores, out);
    nms_kernel<<<NCLS, 1024>>>(boxes, out);
}

// round 6
// speedup vs baseline: 1.0136x; 1.0136x over previous
#include <cuda_runtime.h>
#include <stdint.h>

#define N_BOXES 25200
#define NCLS 80
#define MAXB 100
#define CAP 384          // max candidates per window
#define W   12           // CAP/32 bitmask words per row
#define SORTP_MAX 512
#define NBINS 256
#define TARGET 320

// Output layout (float32 concatenation of the reference tuple):
//   [0, 100800)               boxes copy               (1, 25200, 4)
//   [100800, 2116800)         box_scores transposed    (1, 80, 25200)
//   [2116800, 2140800)        nms_final as f32         (1, 8000, 3)
#define OFF_T   100800
#define OFF_NMS (100800 + NCLS * N_BOXES)

// ---------------------------------------------------------------------------
// Kernel 1: copy boxes + transpose scores [25200,80] -> [80,25200]
// ---------------------------------------------------------------------------
#define TBLK 197  // transpose blocks, 128 rows each (197*128 >= 25200)

__global__ void prep_kernel(const float* __restrict__ boxes,
                            const float* __restrict__ scores,
                            float* __restrict__ out) {
    if (blockIdx.x < TBLK) {
        __shared__ float tile[128][81];  // pad to 81: stride coprime with 32 banks
        int n0 = blockIdx.x * 128;
        int rows = min(128, N_BOXES - n0);
        for (int i = threadIdx.x; i < rows * 80; i += blockDim.x)
            tile[i / 80][i % 80] = scores[n0 * 80 + i];
        __syncthreads();
        float* outT = out + OFF_T;
        for (int i = threadIdx.x; i < 80 * rows; i += blockDim.x) {
            int c = i / rows, dn = i % rows;
            outT[c * N_BOXES + n0 + dn] = tile[dn][c];
        }
    } else {
        int b = blockIdx.x - TBLK;
        const float4* src = (const float4*)boxes;
        float4* dst = (float4*)out;
        int stride = (gridDim.x - TBLK) * blockDim.x;
        for (int i = b * blockDim.x + threadIdx.x; i < N_BOXES; i += stride)
            dst[i] = src[i];
    }
}

// ---------------------------------------------------------------------------
// Kernel 2: one block per class. Sorted window + parallel mask NMS.
// ---------------------------------------------------------------------------
__global__ __launch_bounds__(1024, 1) void nms_kernel(const float* __restrict__ boxes,
                                                      float* __restrict__ out) {
    const int c = blockIdx.x;
    const float* row = out + OFF_T + c * N_BOXES;      // transposed scores
    float* nmsout = out + OFF_NMS + c * (MAXB * 3);

    __shared__ int hist[NBINS];
    __shared__ unsigned long long key[SORTP_MAX];
    __shared__ int bidx[CAP];
    __shared__ float by1[CAP], bx1[CAP], by2[CAP], bx2[CAP], bar[CAP];
    __shared__ unsigned int mask[CAP * W];             // mask[q][chunk]
    __shared__ unsigned int removed[W];
    __shared__ float sy1[MAXB], sx1[MAXB], sy2[MAXB], sx2[MAXB], sar[MAXB];
    __shared__ int sidx[MAXB];
    __shared__ int sh_m, sh_sel, sh_lo, sh_hi;

    const int tid = threadIdx.x;
    const int wid = tid >> 5;
    const int lane = tid & 31;

    for (int i = tid; i < NBINS; i += 1024) hist[i] = 0;
    if (tid == 0) { sh_sel = 0; sh_hi = NBINS; }
    __syncthreads();

    // Histogram of scores >= 0.6 into 256 bins over [0.6, 1.0)
    for (int n = tid; n < N_BOXES; n += 1024) {
        float s = row[n];
        if (s >= 0.6f) {
            int b = (int)((s - 0.6f) * 640.0f);
            b = max(0, min(NBINS - 1, b));
            atomicAdd(&hist[b], 1);
        }
    }
    __syncthreads();

    // Window loop (almost always a single iteration)
    while (sh_sel < MAXB && sh_hi > 0) {
        if (tid == 0) {
            int hi = sh_hi, lo = hi, acc = 0;
            while (lo > 0 && acc + hist[lo - 1] <= TARGET) { acc += hist[lo - 1]; lo--; }
            if (lo == hi) lo = hi - 1;   // oversized single bin: take it anyway
            sh_lo = lo;
            sh_m = 0;
        }
        if (tid < W) removed[tid] = 0u;
        __syncthreads();
        const int lo = sh_lo, hi = sh_hi;

        // Gather keys for candidates in bin window [lo, hi)
        for (int n = tid; n < N_BOXES; n += 1024) {
            float s = row[n];
            if (s >= 0.6f) {
                int b = (int)((s - 0.6f) * 640.0f);
                b = max(0, min(NBINS - 1, b));
                if (b >= lo && b < hi) {
                    int p = atomicAdd(&sh_m, 1);
                    if (p < CAP) {
                        unsigned int sb = __float_as_uint(s);  // positive floats: monotonic
                        key[p] = ((unsigned long long)sb << 32) | (unsigned int)(~(unsigned int)n);
                    }
                }
            }
        }
        __syncthreads();
        const int m = min(sh_m, CAP);

        if (m > 0) {
            int P = 1; while (P < m) P <<= 1; if (P < 2) P = 2;
            for (int i = m + tid; i < P; i += 1024) key[i] = 0ULL;  // sink padding
            __syncthreads();

            // Bitonic sort descending, P <= 512
            for (int k = 2; k <= P; k <<= 1) {
                for (int j = k >> 1; j > 0; j >>= 1) {
                    for (int i = tid; i < P; i += 1024) {
                        int ixj = i ^ j;
                        if (ixj > i) {
                            unsigned long long a = key[i], b2 = key[ixj];
                            bool up = ((i & k) == 0);
                            if (up ? (a < b2) : (a > b2)) { key[i] = b2; key[ixj] = a; }
                        }
                    }
                    __syncthreads();
                }
            }

            // Gather boxes for sorted candidates
            for (int r = tid; r < m; r += 1024) {
                int n = (int)(~(unsigned int)(key[r] & 0xffffffffULL));
                bidx[r] = n;
                float y1 = boxes[n * 4 + 0], x1 = boxes[n * 4 + 1];
                float y2 = boxes[n * 4 + 2], x2 = boxes[n * 4 + 3];
                by1[r] = y1; bx1[r] = x1; by2[r] = y2; bx2[r] = x2;
                bar[r] = __fmul_rn(y2 - y1, x2 - x1);  // exact ref semantics, no FMA
            }
            __syncthreads();

            // Cross-window: pre-remove candidates suppressed by already-selected
            const int sel0 = sh_sel;
            if (sel0 > 0) {
                for (int r = wid; r < m; r += 32) {
                    float cy1 = by1[r], cx1 = bx1[r], cy2 = by2[r], cx2 = bx2[r], ca = bar[r];
                    bool sup = false;
                    for (int t = lane; t < sel0; t += 32) {
                        float iy1 = fmaxf(sy1[t], cy1);
                        float ix1 = fmaxf(sx1[t], cx1);
                        float iy2 = fminf(sy2[t], cy2);
                        float ix2 = fminf(sx2[t], cx2);
                        float inter = __fmul_rn(fmaxf(iy2 - iy1, 0.0f), fmaxf(ix2 - ix1, 0.0f));
                        float uni = sar[t] + ca - inter;
                        float iou = __fdiv_rn(inter, fmaxf(uni, 1e-9f));
                        if (iou > 0.5f) sup = true;
                    }
                    if (__ballot_sync(0xffffffffu, sup) != 0u && lane == 0)
                        atomicOr(&removed[r >> 5], 1u << (r & 31));
                }
            }

            // Phase A: pairwise suppression masks. Warp per row q; one ballot
            // per 32-candidate chunk. Row q written only by its warp -> plain store.
            for (int q = wid; q < m; q += 32) {
                float qy1 = by1[q], qx1 = bx1[q], qy2 = by2[q], qx2 = bx2[q], qa = bar[q];
                for (int r0 = 0; r0 < W * 32; r0 += 32) {
                    int r = r0 + lane;
                    bool pred = false;
                    if (r > q && r < m) {
                        float iy1 = fmaxf(qy1, by1[r]);
                        float ix1 = fmaxf(qx1, bx1[r]);
                        float iy2 = fminf(qy2, by2[r]);
                        float ix2 = fminf(qx2, bx2[r]);
                        float inter = __fmul_rn(fmaxf(iy2 - iy1, 0.0f), fmaxf(ix2 - ix1, 0.0f));
                        float uni = qa + bar[r] - inter;   // selected-first order, adds only
                        float iou = __fdiv_rn(inter, fmaxf(uni, 1e-9f));
                        pred = (iou > 0.5f);
                    }
                    unsigned int bits = __ballot_sync(0xffffffffu, pred);
                    if (lane == 0) mask[q * W + (r0 >> 5)] = bits;
                }
            }
            __syncthreads();

            // Phase B: serial bitmask greedy scan (warp 0)
            if (tid < 32) {
                int sel = sh_sel;
                for (int q = 0; q < m && sel < MAXB; ++q) {
                    unsigned int rw = removed[q >> 5];     // broadcast smem read
                    if (!((rw >> (q & 31)) & 1u)) {
                        if (lane == 0) {
                            sidx[sel] = bidx[q];
                            sy1[sel] = by1[q]; sx1[sel] = bx1[q];
                            sy2[sel] = by2[q]; sx2[sel] = bx2[q];
                            sar[sel] = bar[q];
                        }
                        if (lane < W) removed[lane] |= mask[q * W + lane];
                        sel++;
                    }
                    __syncwarp();
                }
                if (lane == 0) sh_sel = sel;
            }
        }
        __syncthreads();
        if (tid == 0) sh_hi = sh_lo;
        __syncthreads();
    }

    // Emit nms_final rows for this class: [0, c, idx] or [-1,-1,-1]
    const int sel = sh_sel;
    for (int j = tid; j < MAXB; j += 1024) {
        float* o = nmsout + j * 3;
        if (j < sel) { o[0] = 0.0f; o[1] = (float)c; o[2] = (float)sidx[j]; }
        else         { o[0] = -1.0f; o[1] = -1.0f; o[2] = -1.0f; }
    }
}

// ---------------------------------------------------------------------------
extern "C" void kernel_launch(void* const* d_in, const int* in_sizes, int n_in,
                              void* d_out, int out_size) {
    const float* boxes  = (const float*)d_in[0];   // (25200, 4)
    const float* scores = (const float*)d_in[1];   // (25200, 80)
    float* out = (float*)d_out;

    prep_kernel<<<TBLK + 25, 256>>>(boxes, scores, out);
    nms_kernel<<<NCLS, 1024>>>(boxes, out);
}